// round 7
// baseline (speedup 1.0000x reference)
#include <cuda_runtime.h>
#include <math.h>

#define NM 10000
#define ND 552
#define LDA 560          // padded row length of augmented matrix (553 cols used)
#define NB 32
#define NPANEL 18        // 17*32 + 8 = 552
#define KS 5             // k-split for the small GEMM (F @ P)

// ---------------- device scratch (static; no allocation allowed) ----------------
__device__ float g_P[(size_t)NM * ND];          // 22.1 MB  pushforward_cov
__device__ float g_Bpart[(size_t)KS * ND * ND]; // 6.1 MB   k-split partials of F@P
__device__ float g_Aaug[(size_t)ND * LDA];      // 1.24 MB  [A | r] augmented
__device__ float g_rorig[ND];                   // prior misfit (unpermuted)
__device__ float g_tmp[ND];                     // solution A^{-1} r

// =====================================================================
// Kernel 1: P = sigma^2 * exp(c*D) @ F^T       (10000 x 552)
// Tile 128x64, K-chunk 16, 256 threads, 8x4 micro-tile.
// =====================================================================
__global__ __launch_bounds__(256, 3) void kP(const float* __restrict__ D,
                                             const float* __restrict__ F,
                                             const float* __restrict__ lsp,
                                             const float* __restrict__ sgp)
{
    __shared__ float Ds[16][132];   // K x M (padded stride 132 = 33 banks)
    __shared__ float Fs[16][68];    // K x N

    const int tid  = threadIdx.x;
    const int m0   = blockIdx.y * 128;
    const int j0   = blockIdx.x * 64;

    const float l  = lsp[0];
    const float c  = -0.5f / (l * l);
    const float sg = sgp[0];
    const float s2 = sg * sg;

    const int trow = tid >> 4;      // 0..15 -> 8 rows each
    const int tcol = tid & 15;      // 0..15 -> 4 cols each

    // D loader: 2 float4 per thread (128 rows x 16 k = 512 float4)
    const int q0  = tid * 2;
    const int ar0 = q0 >> 2,        ak0 = (q0 & 3) * 4;
    const int ar1 = (q0 + 1) >> 2,  ak1 = ((q0 + 1) & 3) * 4;
    const bool av0 = (m0 + ar0) < NM;
    const bool av1 = (m0 + ar1) < NM;
    const float* Dp0 = D + (size_t)(m0 + ar0) * NM + ak0;
    const float* Dp1 = D + (size_t)(m0 + ar1) * NM + ak1;

    // F loader: 1 float4 per thread (64 rows of F x 16 k)
    const int fj = tid >> 2, fk = (tid & 3) * 4;
    const bool fv = (j0 + fj) < ND;
    const float* Fp = F + (size_t)(j0 + fj) * NM + fk;

    float acc[8][4];
#pragma unroll
    for (int i = 0; i < 8; i++)
#pragma unroll
        for (int j = 0; j < 4; j++) acc[i][j] = 0.f;

    for (int k0 = 0; k0 < NM; k0 += 16) {
        __syncthreads();
        float4 d0 = av0 ? *(const float4*)(Dp0 + k0) : make_float4(0.f, 0.f, 0.f, 0.f);
        float4 d1 = av1 ? *(const float4*)(Dp1 + k0) : make_float4(0.f, 0.f, 0.f, 0.f);
        float4 f  = fv  ? *(const float4*)(Fp  + k0) : make_float4(0.f, 0.f, 0.f, 0.f);

        Ds[ak0 + 0][ar0] = s2 * __expf(c * d0.x);
        Ds[ak0 + 1][ar0] = s2 * __expf(c * d0.y);
        Ds[ak0 + 2][ar0] = s2 * __expf(c * d0.z);
        Ds[ak0 + 3][ar0] = s2 * __expf(c * d0.w);
        Ds[ak1 + 0][ar1] = s2 * __expf(c * d1.x);
        Ds[ak1 + 1][ar1] = s2 * __expf(c * d1.y);
        Ds[ak1 + 2][ar1] = s2 * __expf(c * d1.z);
        Ds[ak1 + 3][ar1] = s2 * __expf(c * d1.w);

        Fs[fk + 0][fj] = f.x;
        Fs[fk + 1][fj] = f.y;
        Fs[fk + 2][fj] = f.z;
        Fs[fk + 3][fj] = f.w;
        __syncthreads();

#pragma unroll
        for (int kk = 0; kk < 16; kk++) {
            float4 a0 = *(const float4*)&Ds[kk][trow * 8];
            float4 a1 = *(const float4*)&Ds[kk][trow * 8 + 4];
            float4 b  = *(const float4*)&Fs[kk][tcol * 4];
            float av[8] = {a0.x, a0.y, a0.z, a0.w, a1.x, a1.y, a1.z, a1.w};
            float bv[4] = {b.x, b.y, b.z, b.w};
#pragma unroll
            for (int i = 0; i < 8; i++)
#pragma unroll
                for (int j = 0; j < 4; j++) acc[i][j] += av[i] * bv[j];
        }
    }

#pragma unroll
    for (int i = 0; i < 8; i++) {
        int m = m0 + trow * 8 + i;
        if (m < NM) {
#pragma unroll
            for (int j = 0; j < 4; j++) {
                int jj = j0 + tcol * 4 + j;
                if (jj < ND) g_P[(size_t)m * ND + jj] = acc[i][j];
            }
        }
    }
}

// =====================================================================
// Kernel 2: Bpart[z] = F[:, z-chunk] @ P[z-chunk, :]   (552 x 552, K=2000 per z)
// Tile 64x64, K-chunk 16, 256 threads, 4x4 micro-tile.
// =====================================================================
__global__ __launch_bounds__(256) void kB(const float* __restrict__ F)
{
    __shared__ float Fst[16][68];
    __shared__ float Ps[16][68];

    const int tid   = threadIdx.x;
    const int j0    = blockIdx.x * 64;
    const int i0    = blockIdx.y * 64;
    const int kbase = blockIdx.z * 2000;

    const int fi = tid >> 2, fk = (tid & 3) * 4;
    const bool fv = (i0 + fi) < ND;
    const int pk = tid >> 4, pj = (tid & 15) * 4;
    const bool pv = (j0 + pj) < ND;

    const int trow = tid >> 4;
    const int tcol = tid & 15;

    float acc[4][4];
#pragma unroll
    for (int i = 0; i < 4; i++)
#pragma unroll
        for (int j = 0; j < 4; j++) acc[i][j] = 0.f;

    for (int kt = 0; kt < 2000; kt += 16) {
        const int k0 = kbase + kt;
        __syncthreads();
        float4 fq = fv ? *(const float4*)(F + (size_t)(i0 + fi) * NM + k0 + fk)
                       : make_float4(0.f, 0.f, 0.f, 0.f);
        Fst[fk + 0][fi] = fq.x;
        Fst[fk + 1][fi] = fq.y;
        Fst[fk + 2][fi] = fq.z;
        Fst[fk + 3][fi] = fq.w;
        float4 pq = pv ? *(const float4*)(g_P + (size_t)(k0 + pk) * ND + j0 + pj)
                       : make_float4(0.f, 0.f, 0.f, 0.f);
        *(float4*)&Ps[pk][pj] = pq;
        __syncthreads();

#pragma unroll
        for (int kk = 0; kk < 16; kk++) {
            float4 a = *(const float4*)&Fst[kk][trow * 4];
            float4 b = *(const float4*)&Ps[kk][tcol * 4];
            float avv[4] = {a.x, a.y, a.z, a.w};
            float bvv[4] = {b.x, b.y, b.z, b.w};
#pragma unroll
            for (int i = 0; i < 4; i++)
#pragma unroll
                for (int j = 0; j < 4; j++) acc[i][j] += avv[i] * bvv[j];
        }
    }

    float* Bp = g_Bpart + (size_t)blockIdx.z * ND * ND;
#pragma unroll
    for (int i = 0; i < 4; i++) {
        int gi = i0 + trow * 4 + i;
        if (gi < ND) {
#pragma unroll
            for (int j = 0; j < 4; j++) {
                int gj = j0 + tcol * 4 + j;
                if (gj < ND) Bp[(size_t)gi * ND + gj] = acc[i][j];
            }
        }
    }
}

// combine k-split partials + data_cov into Aaug columns [0, 552)
__global__ void kC(const float* __restrict__ dcov)
{
    int idx = blockIdx.x * 256 + threadIdx.x;
    if (idx >= ND * ND) return;
    float s = dcov[idx];
#pragma unroll
    for (int z = 0; z < KS; z++) s += g_Bpart[(size_t)z * ND * ND + idx];
    int i = idx / ND, j = idx - i * ND;
    g_Aaug[i * LDA + j] = s;
}

// prior misfit r = d_obs - m0 * rowsum(F); store into Aaug col 552 and g_rorig
__global__ __launch_bounds__(256) void kR(const float* __restrict__ F,
                                          const float* __restrict__ dobs,
                                          const float* __restrict__ m0p)
{
    __shared__ float red[8];
    const int i = blockIdx.x;
    const float* row = F + (size_t)i * NM;
    float s = 0.f;
    for (int t = threadIdx.x; t < NM; t += 256) s += row[t];
#pragma unroll
    for (int o = 16; o; o >>= 1) s += __shfl_down_sync(0xffffffffu, s, o);
    if ((threadIdx.x & 31) == 0) red[threadIdx.x >> 5] = s;
    __syncthreads();
    if (threadIdx.x == 0) {
        float tot = 0.f;
#pragma unroll
        for (int w = 0; w < 8; w++) tot += red[w];
        float r = dobs[i] - m0p[0] * tot;
        g_Aaug[i * LDA + ND] = r;
        g_rorig[i] = r;
    }
}

// =====================================================================
// LU: panel factorization with partial pivoting (1 CTA, panel in smem).
// Row swaps applied to smem panel + trailing global columns [p0+pw, 552].
// Earlier L columns are dead (RHS carried in augmentation) -> not swapped.
// =====================================================================
__global__ __launch_bounds__(512) void kLU(int p0, int pw)
{
    extern __shared__ float sp[];           // (ND-p0) x pw
    const int tid   = threadIdx.x;
    const int nrows = ND - p0;

    for (int idx = tid; idx < nrows * pw; idx += 512)
        sp[idx] = g_Aaug[(p0 + idx / pw) * LDA + p0 + (idx % pw)];
    __syncthreads();

    __shared__ float redv[16];
    __shared__ int   redi[16];
    __shared__ int   s_piv;
    __shared__ float s_pv;

    for (int j = 0; j < pw; j++) {
        // ---- pivot search over column j, rows j..nrows-1 ----
        float best = -1.f; int bi = j;
        for (int i = j + tid; i < nrows; i += 512) {
            float v = fabsf(sp[i * pw + j]);
            if (v > best) { best = v; bi = i; }
        }
#pragma unroll
        for (int o = 16; o; o >>= 1) {
            float ov = __shfl_down_sync(0xffffffffu, best, o);
            int   oi = __shfl_down_sync(0xffffffffu, bi,   o);
            if (ov > best) { best = ov; bi = oi; }
        }
        if ((tid & 31) == 0) { redv[tid >> 5] = best; redi[tid >> 5] = bi; }
        __syncthreads();
        if (tid < 32) {
            float b2 = (tid < 16) ? redv[tid] : -1.f;
            int   i2 = (tid < 16) ? redi[tid] : j;
#pragma unroll
            for (int o = 8; o; o >>= 1) {
                float ov = __shfl_down_sync(0xffffffffu, b2, o);
                int   oi = __shfl_down_sync(0xffffffffu, i2, o);
                if (ov > b2) { b2 = ov; i2 = oi; }
            }
            if (tid == 0) { s_piv = i2; s_pv = sp[i2 * pw + j]; }
        }
        __syncthreads();
        const int piv = s_piv;
        const float pv = s_pv;

        if (piv != j) {
            if (tid < pw) {   // swap smem panel rows
                float t = sp[j * pw + tid];
                sp[j * pw + tid] = sp[piv * pw + tid];
                sp[piv * pw + tid] = t;
            }
            const int gr1 = (p0 + j) * LDA, gr2 = (p0 + piv) * LDA;
            for (int c = p0 + pw + tid; c <= ND; c += 512) {  // trailing cols incl. rhs
                float t1 = g_Aaug[gr1 + c];
                g_Aaug[gr1 + c] = g_Aaug[gr2 + c];
                g_Aaug[gr2 + c] = t1;
            }
        }
        __syncthreads();

        // ---- scale + rank-1 update inside panel ----
        const float inv = 1.f / pv;
        for (int i = j + 1 + tid; i < nrows; i += 512) {
            float lij = sp[i * pw + j] * inv;
            sp[i * pw + j] = lij;
            for (int jj = j + 1; jj < pw; jj++)
                sp[i * pw + jj] -= lij * sp[j * pw + jj];
        }
        __syncthreads();
    }

    for (int idx = tid; idx < nrows * pw; idx += 512)
        g_Aaug[(p0 + idx / pw) * LDA + p0 + (idx % pw)] = sp[idx];
}

// U12 = L11^{-1} A12 over trailing columns (incl. rhs col 552)
__global__ __launch_bounds__(128) void kTRSM(int p0, int pw)
{
    __shared__ float Ls[32][33];
    const int tid = threadIdx.x;
    for (int idx = tid; idx < 32 * 33; idx += 128) ((float*)Ls)[idx] = 0.f;
    __syncthreads();
    for (int idx = tid; idx < pw * pw; idx += 128)
        Ls[idx / pw][idx % pw] = g_Aaug[(p0 + idx / pw) * LDA + p0 + (idx % pw)];
    __syncthreads();

    const int c = p0 + pw + blockIdx.x * 128 + tid;
    if (c > ND) return;

    float v[32];
#pragma unroll
    for (int i = 0; i < 32; i++) v[i] = (i < pw) ? g_Aaug[(p0 + i) * LDA + c] : 0.f;
#pragma unroll
    for (int k = 0; k < 32; k++) {
        if (k >= pw) break;
        float vk = v[k];
#pragma unroll
        for (int i = 0; i < 32; i++)
            if (i > k) v[i] -= Ls[i][k] * vk;
    }
#pragma unroll
    for (int i = 0; i < 32; i++)
        if (i < pw) g_Aaug[(p0 + i) * LDA + c] = v[i];
}

// A22 -= L21 @ U12   (tiles 32x32, K = pw)
__global__ __launch_bounds__(256) void kG(int p0, int pw)
{
    __shared__ float Ls[32][33];
    __shared__ float Us[32][36];
    const int tid = threadIdx.x;
    const int r0  = p0 + pw;
    const int gi0 = r0 + blockIdx.x * 32;
    const int gj0 = r0 + blockIdx.y * 32;

    for (int idx = tid; idx < 32 * 32; idx += 256) {
        int i = idx >> 5, k = idx & 31;
        float v = 0.f;
        if (k < pw && gi0 + i < ND) v = g_Aaug[(gi0 + i) * LDA + p0 + k];
        Ls[i][k] = v;
    }
    for (int idx = tid; idx < 32 * 32; idx += 256) {
        int k = idx >> 5, jn = idx & 31;
        float v = 0.f;
        if (k < pw && gj0 + jn <= ND) v = g_Aaug[(p0 + k) * LDA + gj0 + jn];
        Us[k][jn] = v;
    }
    __syncthreads();

    const int mi = tid >> 3;
    const int nj = (tid & 7) * 4;
    float a0 = 0.f, a1 = 0.f, a2 = 0.f, a3 = 0.f;
    for (int k = 0; k < pw; k++) {
        float a = Ls[mi][k];
        a0 += a * Us[k][nj + 0];
        a1 += a * Us[k][nj + 1];
        a2 += a * Us[k][nj + 2];
        a3 += a * Us[k][nj + 3];
    }
    const int gi = gi0 + mi;
    if (gi < ND) {
        if (gj0 + nj + 0 <= ND) g_Aaug[gi * LDA + gj0 + nj + 0] -= a0;
        if (gj0 + nj + 1 <= ND) g_Aaug[gi * LDA + gj0 + nj + 1] -= a1;
        if (gj0 + nj + 2 <= ND) g_Aaug[gi * LDA + gj0 + nj + 2] -= a2;
        if (gj0 + nj + 3 <= ND) g_Aaug[gi * LDA + gj0 + nj + 3] -= a3;
    }
}

// blocked back-substitution U x = y, logdet = sum log|U_kk|, ll -> out[0]
__global__ __launch_bounds__(576) void kBack(float* __restrict__ out)
{
    __shared__ float x[ND];
    __shared__ float ub[32][33];
    __shared__ float red[18];
    __shared__ float red2[18];
    const int tid = threadIdx.x;

    for (int i = tid; i < ND; i += 576) x[i] = g_Aaug[i * LDA + ND];
    float ld = 0.f;
    for (int k = tid; k < ND; k += 576) ld += logf(fabsf(g_Aaug[k * LDA + k]));
    __syncthreads();

    for (int pb = NPANEL - 1; pb >= 0; pb--) {
        const int p0 = pb * NB;
        const int pw = (pb == NPANEL - 1) ? (ND - p0) : NB;
        for (int idx = tid; idx < pw * pw; idx += 576)
            ub[idx / pw][idx % pw] = g_Aaug[(p0 + idx / pw) * LDA + p0 + (idx % pw)];
        __syncthreads();
        for (int j = pw - 1; j >= 0; j--) {
            if (tid == 0) x[p0 + j] = x[p0 + j] / ub[j][j];
            __syncthreads();
            float xk = x[p0 + j];
            if (tid < j) x[p0 + tid] -= ub[tid][j] * xk;
            __syncthreads();
        }
        for (int i = tid; i < p0; i += 576) {
            float s = 0.f;
            for (int j = 0; j < pw; j++) s += g_Aaug[i * LDA + p0 + j] * x[p0 + j];
            x[i] -= s;
        }
        __syncthreads();
    }

    float dp = 0.f;
    for (int i = tid; i < ND; i += 576) dp += g_rorig[i] * x[i];
#pragma unroll
    for (int o = 16; o; o >>= 1) {
        ld += __shfl_down_sync(0xffffffffu, ld, o);
        dp += __shfl_down_sync(0xffffffffu, dp, o);
    }
    if ((tid & 31) == 0) { red[tid >> 5] = ld; red2[tid >> 5] = dp; }
    __syncthreads();
    if (tid == 0) {
        float tl = 0.f, td = 0.f;
        for (int w = 0; w < 18; w++) { tl += red[w]; td += red2[w]; }
        out[0] = tl + td;
    }
    for (int i = tid; i < ND; i += 576) g_tmp[i] = x[i];
}

// m_posterior = m0 + P @ tmp  (warp per row)
__global__ __launch_bounds__(256) void kM(float* __restrict__ out,
                                          const float* __restrict__ m0p)
{
    __shared__ float sx[ND];
    const int tid = threadIdx.x;
    for (int i = tid; i < ND; i += 256) sx[i] = g_tmp[i];
    __syncthreads();
    const int warp = tid >> 5, lane = tid & 31;
    const int row = blockIdx.x * 8 + warp;
    const float* pr = g_P + (size_t)row * ND;
    float s = 0.f;
    for (int j = lane; j < ND; j += 32) s += pr[j] * sx[j];
#pragma unroll
    for (int o = 16; o; o >>= 1) s += __shfl_down_sync(0xffffffffu, s, o);
    if (lane == 0) out[1 + row] = m0p[0] + s;
}

// =====================================================================
extern "C" void kernel_launch(void* const* d_in, const int* in_sizes, int n_in,
                              void* d_out, int out_size)
{
    const float* D    = (const float*)d_in[0];
    const float* F    = (const float*)d_in[1];
    const float* dobs = (const float*)d_in[2];
    const float* dcov = (const float*)d_in[3];
    const float* m0p  = (const float*)d_in[4];
    const float* lsp  = (const float*)d_in[5];
    const float* sgp  = (const float*)d_in[6];
    float* out = (float*)d_out;

    cudaFuncSetAttribute(kLU, cudaFuncAttributeMaxDynamicSharedMemorySize, ND * NB * 4);

    kP<<<dim3(9, 79), 256>>>(D, F, lsp, sgp);
    kB<<<dim3(9, 9, KS), 256>>>(F);
    kC<<<(ND * ND + 255) / 256, 256>>>(dcov);
    kR<<<ND, 256>>>(F, dobs, m0p);

    for (int p = 0; p < NPANEL; p++) {
        const int p0 = p * NB;
        const int pw = (p == NPANEL - 1) ? (ND - p0) : NB;
        const int nrows = ND - p0;
        kLU<<<1, 512, nrows * pw * 4>>>(p0, pw);
        const int tcols = ND + 1 - (p0 + pw);   // includes rhs column
        if (tcols > 0) kTRSM<<<(tcols + 127) / 128, 128>>>(p0, pw);
        const int m = ND - (p0 + pw);
        if (m > 0) kG<<<dim3((m + 31) / 32, (tcols + 31) / 32), 256>>>(p0, pw);
    }

    kBack<<<1, 576>>>(out);
    kM<<<1250, 256>>>(out, m0p);
}

// round 9
// speedup vs baseline: 1.1941x; 1.1941x over previous
#include <cuda_runtime.h>
#include <cuda_bf16.h>
#include <math.h>
#include <stdint.h>

#define NM 10000
#define ND 552
#define LDA 560          // padded row length of augmented matrix (553 cols used)
#define NB 32
#define NPANEL 18        // 17*32 + 8 = 552
#define KSB 8            // k-split for F @ P
#define NCHUNK 313       // ceil(10000/32)

// ---------------- device scratch (static; no allocation allowed) ----------------
__device__ float          g_Pt[(size_t)ND * NM];           // 22.1 MB  P transposed [j][m]
__device__ __nv_bfloat16  g_Fhi[(size_t)ND * NM];          // 11 MB
__device__ __nv_bfloat16  g_Flo[(size_t)ND * NM];          // 11 MB
__device__ float          g_Bpart[(size_t)KSB * ND * ND];  // 9.8 MB
__device__ float          g_Aaug[(size_t)ND * LDA];        // [A | r]
__device__ float          g_rorig[ND];
__device__ float          g_tmp[ND];

// ===================== helpers ==================
__device__ __forceinline__ uint32_t smem_u32(const void* p) {
    uint32_t a;
    asm("{ .reg .u64 t; cvta.to.shared.u64 t, %1; cvt.u32.u64 %0, t; }" : "=r"(a) : "l"(p));
    return a;
}

__device__ __forceinline__ void ldx4(uint32_t* r, uint32_t addr) {
    asm volatile("ldmatrix.sync.aligned.m8n8.x4.shared.b16 {%0,%1,%2,%3}, [%4];"
                 : "=r"(r[0]), "=r"(r[1]), "=r"(r[2]), "=r"(r[3]) : "r"(addr));
}

__device__ __forceinline__ void mma16816(float* c, const uint32_t* a, uint32_t b0, uint32_t b1) {
    asm volatile(
        "mma.sync.aligned.m16n8k16.row.col.f32.bf16.bf16.f32 "
        "{%0,%1,%2,%3}, {%4,%5,%6,%7}, {%8,%9}, {%0,%1,%2,%3};"
        : "+f"(c[0]), "+f"(c[1]), "+f"(c[2]), "+f"(c[3])
        : "r"(a[0]), "r"(a[1]), "r"(a[2]), "r"(a[3]), "r"(b0), "r"(b1));
}

__device__ __forceinline__ void split2(float a, float b, uint32_t& hv, uint32_t& lv) {
    __nv_bfloat16 ha = __float2bfloat16(a), hb = __float2bfloat16(b);
    __nv_bfloat162 hh; hh.x = ha; hh.y = hb;
    hv = *(uint32_t*)&hh;
    __nv_bfloat162 ll;
    ll.x = __float2bfloat16(a - __bfloat162float(ha));
    ll.y = __float2bfloat16(b - __bfloat162float(hb));
    lv = *(uint32_t*)&ll;
}

// SMEM: Ahi [128][40] bf16 @0, Alo @10240, Bhi @20480, Blo @30720 (bytes)
// epilogue staging reuses the same buffer: float [128][68] = 34816 B
#define SM_BYTES 40960
#define A_LO_OFF 10240
#define B_HI_OFF 20480
#define B_LO_OFF 30720

// ============================ F -> bf16 hi/lo split ==========================
__global__ void kFsplit(const float* __restrict__ F) {
    int idx = blockIdx.x * 256 + threadIdx.x;
    if (idx >= ND * NM) return;
    float f = F[idx];
    __nv_bfloat16 h = __float2bfloat16(f);
    g_Fhi[idx] = h;
    g_Flo[idx] = __float2bfloat16(f - __bfloat162float(h));
}

// =====================================================================
// kPmma: Pt[j][m] = (s2*exp(c*D)) @ F^T via mma.sync bf16-split (3 passes)
// grid (79 m-tiles of 128, 5 j-tiles of 128), 256 threads
// =====================================================================
__global__ __launch_bounds__(256, 1) void kPmma(const float* __restrict__ Dm,
                                                const float* __restrict__ lsp,
                                                const float* __restrict__ sgp) {
    __shared__ __align__(16) char sm[SM_BYTES];
    __nv_bfloat16* Ahi = (__nv_bfloat16*)sm;
    __nv_bfloat16* Alo = (__nv_bfloat16*)(sm + A_LO_OFF);
    __nv_bfloat16* Bhi = (__nv_bfloat16*)(sm + B_HI_OFF);
    __nv_bfloat16* Blo = (__nv_bfloat16*)(sm + B_LO_OFF);
    const uint32_t sb = smem_u32(sm);

    const int tid = threadIdx.x, lane = tid & 31, wid = tid >> 5;
    const int m0 = blockIdx.x * 128, j0 = blockIdx.y * 128;

    const float l = lsp[0];
    const float cexp = -0.5f / (l * l);
    const float s2 = sgp[0] * sgp[0];

    // loaders: each thread owns one row-half (16 k) of A(=D) and B(=F)
    const int lr = tid >> 1, lk = (tid & 1) * 16;
    const bool mval = (m0 + lr) < NM;
    const bool nval = (j0 + lr) < ND;
    const float* Dp = Dm + (size_t)(m0 + lr) * NM + lk;
    const __nv_bfloat16* Fh = g_Fhi + (size_t)(j0 + lr) * NM + lk;
    const __nv_bfloat16* Fl = g_Flo + (size_t)(j0 + lr) * NM + lk;

    float4 dv[4];
    bool dok[4];
    uint4 fh[2], fl[2];

#define LOADCH_P(k0)                                                          \
    {                                                                         \
        _Pragma("unroll")                                                     \
        for (int i = 0; i < 4; i++) {                                         \
            int kk = (k0) + lk + i * 4;                                       \
            dok[i] = mval && (kk < NM);                                       \
            dv[i] = dok[i] ? *(const float4*)(Dp + (k0) + i * 4)              \
                           : make_float4(0.f, 0.f, 0.f, 0.f);                 \
        }                                                                     \
        _Pragma("unroll")                                                     \
        for (int i = 0; i < 2; i++) {                                         \
            int kk = (k0) + lk + i * 8;                                       \
            bool ok = nval && (kk < NM);                                      \
            fh[i] = ok ? *(const uint4*)(Fh + (k0) + i * 8) : make_uint4(0, 0, 0, 0); \
            fl[i] = ok ? *(const uint4*)(Fl + (k0) + i * 8) : make_uint4(0, 0, 0, 0); \
        }                                                                     \
    }

    const int sA = lr * 40 + lk;   // element offset in padded smem row

    // warp tiling: 4 m-warps x 2 n-warps; warp tile 32m x 64n
    const int wm = (wid & 3) * 32, wn = (wid >> 2) * 64;
    const uint32_t aAoff = (uint32_t)((wm + (lane & 15)) * 40 + ((lane >> 4) & 1) * 8) * 2;
    const uint32_t aBoff = (uint32_t)((wn + ((lane >> 4) << 3) + (lane & 7)) * 40
                                      + ((lane >> 3) & 1) * 8) * 2;

    float acc[2][8][4];
#pragma unroll
    for (int a = 0; a < 2; a++)
#pragma unroll
        for (int b = 0; b < 8; b++)
#pragma unroll
            for (int d = 0; d < 4; d++) acc[a][b][d] = 0.f;

    LOADCH_P(0);

    for (int ch = 0; ch < NCHUNK; ++ch) {
        // ---- STS current chunk (exp + split for A; copy for B) ----
#pragma unroll
        for (int i = 0; i < 4; i++) {
            float e0 = dok[i] ? s2 * __expf(cexp * dv[i].x) : 0.f;
            float e1 = dok[i] ? s2 * __expf(cexp * dv[i].y) : 0.f;
            float e2 = dok[i] ? s2 * __expf(cexp * dv[i].z) : 0.f;
            float e3 = dok[i] ? s2 * __expf(cexp * dv[i].w) : 0.f;
            uint32_t h01, l01, h23, l23;
            split2(e0, e1, h01, l01);
            split2(e2, e3, h23, l23);
            *(uint2*)(Ahi + sA + i * 4) = make_uint2(h01, h23);
            *(uint2*)(Alo + sA + i * 4) = make_uint2(l01, l23);
        }
        *(uint4*)(Bhi + sA) = fh[0];
        *(uint4*)(Bhi + sA + 8) = fh[1];
        *(uint4*)(Blo + sA) = fl[0];
        *(uint4*)(Blo + sA + 8) = fl[1];
        __syncthreads();

        if (ch + 1 < NCHUNK) LOADCH_P((ch + 1) * 32);

        // ---- compute 2 k-steps of 16 ----
#pragma unroll
        for (int kst = 0; kst < 2; ++kst) {
            uint32_t ah[2][4], al[2][4];
#pragma unroll
            for (int mt = 0; mt < 2; ++mt) {
                uint32_t o = aAoff + mt * 1280 + kst * 32;
                ldx4(ah[mt], sb + o);
                ldx4(al[mt], sb + A_LO_OFF + o);
            }
#pragma unroll
            for (int nh = 0; nh < 2; ++nh) {
                uint32_t bh[2][4], bl[2][4];
#pragma unroll
                for (int ng = 0; ng < 2; ++ng) {
                    uint32_t o = aBoff + nh * 2560 + ng * 1280 + kst * 32;
                    ldx4(bh[ng], sb + B_HI_OFF + o);
                    ldx4(bl[ng], sb + B_LO_OFF + o);
                }
#pragma unroll
                for (int mt = 0; mt < 2; mt++)
#pragma unroll
                    for (int nt = 0; nt < 4; nt++) {
                        float* cc = acc[mt][nh * 4 + nt];
                        uint32_t b0h = bh[nt >> 1][(nt & 1) * 2];
                        uint32_t b1h = bh[nt >> 1][(nt & 1) * 2 + 1];
                        uint32_t b0l = bl[nt >> 1][(nt & 1) * 2];
                        uint32_t b1l = bl[nt >> 1][(nt & 1) * 2 + 1];
                        mma16816(cc, ah[mt], b0h, b1h);
                        mma16816(cc, ah[mt], b0l, b1l);
                        mma16816(cc, al[mt], b0h, b1h);
                    }
            }
        }
        __syncthreads();
    }

    // ---- epilogue: transpose via smem staging, write Pt[j][m] coalesced in m ----
    float* stg = (float*)sm;  // [128 n][68 m] per 64-m half
#pragma unroll
    for (int h = 0; h < 2; ++h) {
        __syncthreads();
        if (((wid & 3) >> 1) == h) {
            const int rb = wm - h * 64 + (lane >> 2);
            const int cb = 2 * (lane & 3);
#pragma unroll
            for (int mt = 0; mt < 2; mt++)
#pragma unroll
                for (int nt = 0; nt < 8; nt++) {
                    int r = rb + mt * 16;
                    int c = wn + ((nt >> 2) * 32) + ((nt & 3) * 8) + cb;
                    stg[(c + 0) * 68 + r]     = acc[mt][nt][0];
                    stg[(c + 1) * 68 + r]     = acc[mt][nt][1];
                    stg[(c + 0) * 68 + r + 8] = acc[mt][nt][2];
                    stg[(c + 1) * 68 + r + 8] = acc[mt][nt][3];
                }
        }
        __syncthreads();
#pragma unroll 4
        for (int it = 0; it < 32; ++it) {
            int nr = it * 4 + (tid >> 6);
            int mc = tid & 63;
            int j = j0 + nr, m = m0 + h * 64 + mc;
            if (j < ND && m < NM) g_Pt[(size_t)j * NM + m] = stg[nr * 68 + mc];
        }
    }
}

// =====================================================================
// kBmma: Bpart[z] = F @ P   (A = F hi/lo, B = Pt split on the fly)
// grid (5 i-tiles, 5 j-tiles, 8 z)
// =====================================================================
__global__ __launch_bounds__(256, 1) void kBmma() {
    __shared__ __align__(16) char sm[SM_BYTES];
    __nv_bfloat16* Ahi = (__nv_bfloat16*)sm;
    __nv_bfloat16* Alo = (__nv_bfloat16*)(sm + A_LO_OFF);
    __nv_bfloat16* Bhi = (__nv_bfloat16*)(sm + B_HI_OFF);
    __nv_bfloat16* Blo = (__nv_bfloat16*)(sm + B_LO_OFF);
    const uint32_t sb = smem_u32(sm);

    const int tid = threadIdx.x, lane = tid & 31, wid = tid >> 5;
    const int i0 = blockIdx.x * 128, j0 = blockIdx.y * 128;
    const int z = blockIdx.z;
    const int c0 = z * 40;
    const int c1 = min(NCHUNK, c0 + 40);

    const int lr = tid >> 1, lk = (tid & 1) * 16;
    const bool ival = (i0 + lr) < ND;
    const bool jval = (j0 + lr) < ND;
    const __nv_bfloat16* Fh = g_Fhi + (size_t)(i0 + lr) * NM + lk;
    const __nv_bfloat16* Fl = g_Flo + (size_t)(i0 + lr) * NM + lk;
    const float* Pp = g_Pt + (size_t)(j0 + lr) * NM + lk;

    float4 pv[4];
    bool pok[4];
    uint4 fh[2], fl[2];

#define LOADCH_B(k0)                                                          \
    {                                                                         \
        _Pragma("unroll")                                                     \
        for (int i = 0; i < 2; i++) {                                         \
            int kk = (k0) + lk + i * 8;                                       \
            bool ok = ival && (kk < NM);                                      \
            fh[i] = ok ? *(const uint4*)(Fh + (k0) + i * 8) : make_uint4(0, 0, 0, 0); \
            fl[i] = ok ? *(const uint4*)(Fl + (k0) + i * 8) : make_uint4(0, 0, 0, 0); \
        }                                                                     \
        _Pragma("unroll")                                                     \
        for (int i = 0; i < 4; i++) {                                         \
            int kk = (k0) + lk + i * 4;                                       \
            pok[i] = jval && (kk < NM);                                       \
            pv[i] = pok[i] ? *(const float4*)(Pp + (k0) + i * 4)              \
                           : make_float4(0.f, 0.f, 0.f, 0.f);                 \
        }                                                                     \
    }

    const int sA = lr * 40 + lk;
    const int wm = (wid & 3) * 32, wn = (wid >> 2) * 64;
    const uint32_t aAoff = (uint32_t)((wm + (lane & 15)) * 40 + ((lane >> 4) & 1) * 8) * 2;
    const uint32_t aBoff = (uint32_t)((wn + ((lane >> 4) << 3) + (lane & 7)) * 40
                                      + ((lane >> 3) & 1) * 8) * 2;

    float acc[2][8][4];
#pragma unroll
    for (int a = 0; a < 2; a++)
#pragma unroll
        for (int b = 0; b < 8; b++)
#pragma unroll
            for (int d = 0; d < 4; d++) acc[a][b][d] = 0.f;

    LOADCH_B(c0 * 32);

    for (int ch = c0; ch < c1; ++ch) {
        // A: F hi/lo copy
        *(uint4*)(Ahi + sA) = fh[0];
        *(uint4*)(Ahi + sA + 8) = fh[1];
        *(uint4*)(Alo + sA) = fl[0];
        *(uint4*)(Alo + sA + 8) = fl[1];
        // B: Pt fp32 -> split
#pragma unroll
        for (int i = 0; i < 4; i++) {
            uint32_t h01, l01, h23, l23;
            split2(pv[i].x, pv[i].y, h01, l01);
            split2(pv[i].z, pv[i].w, h23, l23);
            *(uint2*)(Bhi + sA + i * 4) = make_uint2(h01, h23);
            *(uint2*)(Blo + sA + i * 4) = make_uint2(l01, l23);
        }
        __syncthreads();

        if (ch + 1 < c1) LOADCH_B((ch + 1) * 32);

#pragma unroll
        for (int kst = 0; kst < 2; ++kst) {
            uint32_t ah[2][4], al[2][4];
#pragma unroll
            for (int mt = 0; mt < 2; ++mt) {
                uint32_t o = aAoff + mt * 1280 + kst * 32;
                ldx4(ah[mt], sb + o);
                ldx4(al[mt], sb + A_LO_OFF + o);
            }
#pragma unroll
            for (int nh = 0; nh < 2; ++nh) {
                uint32_t bh[2][4], bl[2][4];
#pragma unroll
                for (int ng = 0; ng < 2; ++ng) {
                    uint32_t o = aBoff + nh * 2560 + ng * 1280 + kst * 32;
                    ldx4(bh[ng], sb + B_HI_OFF + o);
                    ldx4(bl[ng], sb + B_LO_OFF + o);
                }
#pragma unroll
                for (int mt = 0; mt < 2; mt++)
#pragma unroll
                    for (int nt = 0; nt < 4; nt++) {
                        float* cc = acc[mt][nh * 4 + nt];
                        uint32_t b0h = bh[nt >> 1][(nt & 1) * 2];
                        uint32_t b1h = bh[nt >> 1][(nt & 1) * 2 + 1];
                        uint32_t b0l = bl[nt >> 1][(nt & 1) * 2];
                        uint32_t b1l = bl[nt >> 1][(nt & 1) * 2 + 1];
                        mma16816(cc, ah[mt], b0h, b1h);
                        mma16816(cc, ah[mt], b0l, b1l);
                        mma16816(cc, al[mt], b0h, b1h);
                    }
            }
        }
        __syncthreads();
    }

    // direct epilogue (row-major Bpart)
    float* Bp = g_Bpart + (size_t)z * ND * ND;
    const int rb = i0 + wm + (lane >> 2);
    const int cb = j0 + wn + 2 * (lane & 3);
#pragma unroll
    for (int mt = 0; mt < 2; mt++)
#pragma unroll
        for (int nt = 0; nt < 8; nt++) {
            int i = rb + mt * 16;
            int c = cb + (nt >> 2) * 32 + (nt & 3) * 8;
            if (c < ND) {
                if (i < ND)
                    *(float2*)(Bp + (size_t)i * ND + c) = make_float2(acc[mt][nt][0], acc[mt][nt][1]);
                if (i + 8 < ND)
                    *(float2*)(Bp + (size_t)(i + 8) * ND + c) = make_float2(acc[mt][nt][2], acc[mt][nt][3]);
            }
        }
}

// combine k-split partials + data_cov into Aaug columns [0, 552)
__global__ void kC(const float* __restrict__ dcov) {
    int idx = blockIdx.x * 256 + threadIdx.x;
    if (idx >= ND * ND) return;
    float s = dcov[idx];
#pragma unroll
    for (int zz = 0; zz < KSB; zz++) s += g_Bpart[(size_t)zz * ND * ND + idx];
    int i = idx / ND, j = idx - i * ND;
    g_Aaug[i * LDA + j] = s;
}

// prior misfit r = d_obs - m0 * rowsum(F)
__global__ __launch_bounds__(256) void kR(const float* __restrict__ F,
                                          const float* __restrict__ dobs,
                                          const float* __restrict__ m0p) {
    __shared__ float red[8];
    const int i = blockIdx.x;
    const float* row = F + (size_t)i * NM;
    float s = 0.f;
    for (int t = threadIdx.x; t < NM; t += 256) s += row[t];
#pragma unroll
    for (int o = 16; o; o >>= 1) s += __shfl_down_sync(0xffffffffu, s, o);
    if ((threadIdx.x & 31) == 0) red[threadIdx.x >> 5] = s;
    __syncthreads();
    if (threadIdx.x == 0) {
        float tot = 0.f;
#pragma unroll
        for (int w = 0; w < 8; w++) tot += red[w];
        float r = dobs[i] - m0p[0] * tot;
        g_Aaug[i * LDA + ND] = r;
        g_rorig[i] = r;
    }
}

// =====================================================================
// LU chain (unchanged from round 7, known-good)
// =====================================================================
__global__ __launch_bounds__(512) void kLU(int p0, int pw) {
    extern __shared__ float sp[];
    const int tid = threadIdx.x;
    const int nrows = ND - p0;

    for (int idx = tid; idx < nrows * pw; idx += 512)
        sp[idx] = g_Aaug[(p0 + idx / pw) * LDA + p0 + (idx % pw)];
    __syncthreads();

    __shared__ float redv[16];
    __shared__ int   redi[16];
    __shared__ int   s_piv;
    __shared__ float s_pv;

    for (int j = 0; j < pw; j++) {
        float best = -1.f; int bi = j;
        for (int i = j + tid; i < nrows; i += 512) {
            float v = fabsf(sp[i * pw + j]);
            if (v > best) { best = v; bi = i; }
        }
#pragma unroll
        for (int o = 16; o; o >>= 1) {
            float ov = __shfl_down_sync(0xffffffffu, best, o);
            int   oi = __shfl_down_sync(0xffffffffu, bi,   o);
            if (ov > best) { best = ov; bi = oi; }
        }
        if ((tid & 31) == 0) { redv[tid >> 5] = best; redi[tid >> 5] = bi; }
        __syncthreads();
        if (tid < 32) {
            float b2 = (tid < 16) ? redv[tid] : -1.f;
            int   i2 = (tid < 16) ? redi[tid] : j;
#pragma unroll
            for (int o = 8; o; o >>= 1) {
                float ov = __shfl_down_sync(0xffffffffu, b2, o);
                int   oi = __shfl_down_sync(0xffffffffu, i2, o);
                if (ov > b2) { b2 = ov; i2 = oi; }
            }
            if (tid == 0) { s_piv = i2; s_pv = sp[i2 * pw + j]; }
        }
        __syncthreads();
        const int piv = s_piv;
        const float pv = s_pv;

        if (piv != j) {
            if (tid < pw) {
                float t = sp[j * pw + tid];
                sp[j * pw + tid] = sp[piv * pw + tid];
                sp[piv * pw + tid] = t;
            }
            const int gr1 = (p0 + j) * LDA, gr2 = (p0 + piv) * LDA;
            for (int cc = p0 + pw + tid; cc <= ND; cc += 512) {
                float t1 = g_Aaug[gr1 + cc];
                g_Aaug[gr1 + cc] = g_Aaug[gr2 + cc];
                g_Aaug[gr2 + cc] = t1;
            }
        }
        __syncthreads();

        const float inv = 1.f / pv;
        for (int i = j + 1 + tid; i < nrows; i += 512) {
            float lij = sp[i * pw + j] * inv;
            sp[i * pw + j] = lij;
            for (int jj = j + 1; jj < pw; jj++)
                sp[i * pw + jj] -= lij * sp[j * pw + jj];
        }
        __syncthreads();
    }

    for (int idx = tid; idx < nrows * pw; idx += 512)
        g_Aaug[(p0 + idx / pw) * LDA + p0 + (idx % pw)] = sp[idx];
}

__global__ __launch_bounds__(128) void kTRSM(int p0, int pw) {
    __shared__ float Ls[32][33];
    const int tid = threadIdx.x;
    for (int idx = tid; idx < 32 * 33; idx += 128) ((float*)Ls)[idx] = 0.f;
    __syncthreads();
    for (int idx = tid; idx < pw * pw; idx += 128)
        Ls[idx / pw][idx % pw] = g_Aaug[(p0 + idx / pw) * LDA + p0 + (idx % pw)];
    __syncthreads();

    const int cc = p0 + pw + blockIdx.x * 128 + tid;
    if (cc > ND) return;

    float v[32];
#pragma unroll
    for (int i = 0; i < 32; i++) v[i] = (i < pw) ? g_Aaug[(p0 + i) * LDA + cc] : 0.f;
#pragma unroll
    for (int k = 0; k < 32; k++) {
        if (k >= pw) break;
        float vk = v[k];
#pragma unroll
        for (int i = 0; i < 32; i++)
            if (i > k) v[i] -= Ls[i][k] * vk;
    }
#pragma unroll
    for (int i = 0; i < 32; i++)
        if (i < pw) g_Aaug[(p0 + i) * LDA + cc] = v[i];
}

__global__ __launch_bounds__(256) void kG(int p0, int pw) {
    __shared__ float Ls[32][33];
    __shared__ float Us[32][36];
    const int tid = threadIdx.x;
    const int r0  = p0 + pw;
    const int gi0 = r0 + blockIdx.x * 32;
    const int gj0 = r0 + blockIdx.y * 32;

    for (int idx = tid; idx < 32 * 32; idx += 256) {
        int i = idx >> 5, k = idx & 31;
        float v = 0.f;
        if (k < pw && gi0 + i < ND) v = g_Aaug[(gi0 + i) * LDA + p0 + k];
        Ls[i][k] = v;
    }
    for (int idx = tid; idx < 32 * 32; idx += 256) {
        int k = idx >> 5, jn = idx & 31;
        float v = 0.f;
        if (k < pw && gj0 + jn <= ND) v = g_Aaug[(p0 + k) * LDA + gj0 + jn];
        Us[k][jn] = v;
    }
    __syncthreads();

    const int mi = tid >> 3;
    const int nj = (tid & 7) * 4;
    float a0 = 0.f, a1 = 0.f, a2 = 0.f, a3 = 0.f;
    for (int k = 0; k < pw; k++) {
        float a = Ls[mi][k];
        a0 += a * Us[k][nj + 0];
        a1 += a * Us[k][nj + 1];
        a2 += a * Us[k][nj + 2];
        a3 += a * Us[k][nj + 3];
    }
    const int gi = gi0 + mi;
    if (gi < ND) {
        if (gj0 + nj + 0 <= ND) g_Aaug[gi * LDA + gj0 + nj + 0] -= a0;
        if (gj0 + nj + 1 <= ND) g_Aaug[gi * LDA + gj0 + nj + 1] -= a1;
        if (gj0 + nj + 2 <= ND) g_Aaug[gi * LDA + gj0 + nj + 2] -= a2;
        if (gj0 + nj + 3 <= ND) g_Aaug[gi * LDA + gj0 + nj + 3] -= a3;
    }
}

__global__ __launch_bounds__(576) void kBack(float* __restrict__ out) {
    __shared__ float x[ND];
    __shared__ float ub[32][33];
    __shared__ float red[18];
    __shared__ float red2[18];
    const int tid = threadIdx.x;

    for (int i = tid; i < ND; i += 576) x[i] = g_Aaug[i * LDA + ND];
    float ld = 0.f;
    for (int k = tid; k < ND; k += 576) ld += logf(fabsf(g_Aaug[k * LDA + k]));
    __syncthreads();

    for (int pb = NPANEL - 1; pb >= 0; pb--) {
        const int p0 = pb * NB;
        const int pw = (pb == NPANEL - 1) ? (ND - p0) : NB;
        for (int idx = tid; idx < pw * pw; idx += 576)
            ub[idx / pw][idx % pw] = g_Aaug[(p0 + idx / pw) * LDA + p0 + (idx % pw)];
        __syncthreads();
        for (int j = pw - 1; j >= 0; j--) {
            if (tid == 0) x[p0 + j] = x[p0 + j] / ub[j][j];
            __syncthreads();
            float xk = x[p0 + j];
            if (tid < j) x[p0 + tid] -= ub[tid][j] * xk;
            __syncthreads();
        }
        for (int i = tid; i < p0; i += 576) {
            float s = 0.f;
            for (int j = 0; j < pw; j++) s += g_Aaug[i * LDA + p0 + j] * x[p0 + j];
            x[i] -= s;
        }
        __syncthreads();
    }

    float dp = 0.f;
    for (int i = tid; i < ND; i += 576) dp += g_rorig[i] * x[i];
#pragma unroll
    for (int o = 16; o; o >>= 1) {
        ld += __shfl_down_sync(0xffffffffu, ld, o);
        dp += __shfl_down_sync(0xffffffffu, dp, o);
    }
    if ((tid & 31) == 0) { red[tid >> 5] = ld; red2[tid >> 5] = dp; }
    __syncthreads();
    if (tid == 0) {
        float tl = 0.f, td = 0.f;
        for (int w = 0; w < 18; w++) { tl += red[w]; td += red2[w]; }
        out[0] = tl + td;
    }
    for (int i = tid; i < ND; i += 576) g_tmp[i] = x[i];
}

// m_posterior = m0 + P @ tmp, via Pt (thread per model row, coalesced)
__global__ __launch_bounds__(256) void kM(float* __restrict__ out,
                                          const float* __restrict__ m0p) {
    __shared__ float sx[ND];
    const int tid = threadIdx.x;
    for (int i = tid; i < ND; i += 256) sx[i] = g_tmp[i];
    __syncthreads();
    const int m = blockIdx.x * 256 + tid;
    if (m >= NM) return;
    float s = 0.f;
#pragma unroll 4
    for (int j = 0; j < ND; j++) s += g_Pt[(size_t)j * NM + m] * sx[j];
    out[1 + m] = m0p[0] + s;
}

// =====================================================================
extern "C" void kernel_launch(void* const* d_in, const int* in_sizes, int n_in,
                              void* d_out, int out_size) {
    const float* D    = (const float*)d_in[0];
    const float* F    = (const float*)d_in[1];
    const float* dobs = (const float*)d_in[2];
    const float* dcov = (const float*)d_in[3];
    const float* m0p  = (const float*)d_in[4];
    const float* lsp  = (const float*)d_in[5];
    const float* sgp  = (const float*)d_in[6];
    float* out = (float*)d_out;

    cudaFuncSetAttribute(kLU, cudaFuncAttributeMaxDynamicSharedMemorySize, ND * NB * 4);

    kFsplit<<<(ND * NM + 255) / 256, 256>>>(F);
    kPmma<<<dim3(79, 5), 256>>>(D, lsp, sgp);
    kBmma<<<dim3(5, 5, KSB), 256>>>();
    kC<<<(ND * ND + 255) / 256, 256>>>(dcov);
    kR<<<ND, 256>>>(F, dobs, m0p);

    for (int p = 0; p < NPANEL; p++) {
        const int p0 = p * NB;
        const int pw = (p == NPANEL - 1) ? (ND - p0) : NB;
        const int nrows = ND - p0;
        kLU<<<1, 512, nrows * pw * 4>>>(p0, pw);
        const int tcols = ND + 1 - (p0 + pw);
        if (tcols > 0) kTRSM<<<(tcols + 127) / 128, 128>>>(p0, pw);
        const int m = ND - (p0 + pw);
        if (m > 0) kG<<<dim3((m + 31) / 32, (tcols + 31) / 32), 256>>>(p0, pw);
    }

    kBack<<<1, 576>>>(out);
    kM<<<(NM + 255) / 256, 256>>>(out, m0p);
}